// round 4
// baseline (speedup 1.0000x reference)
#include <cuda_runtime.h>

#define NBINS  10
#define NSLOTS 11          // 10 real bins + dead slot for out-of-range
#define NT     256
#define NCOPY  2           // sub-histograms per thread (break smem RAW chains)
#define GRID   608         // 4 CTAs * 152 SMs (GB300)

// Per-block partials: every block overwrites its own slot -> no zeroing pass.
__device__ float2   g_part[GRID][NBINS];
__device__ unsigned g_ticket;   // zero-init at load; last block resets it each call

__device__ __forceinline__ void ghmc_acc(float p, float t, float2* __restrict__ h) {
    // slot = min(floor(10*|p-t|), 10); slot 10 (g >= 1) is discarded.
    float g10 = fabsf(p - t) * 10.0f;
    int  slot = min((int)g10, NSLOTS - 1);

    // bce = t*p - softplus(p);  softplus(p) = max(p,0) + log(1+exp(-|p|))
    float e   = __expf(-fabsf(p));
    float l   = __logf(1.0f + e);
    float bce = t * p - fmaxf(p, 0.0f) - l;

    float2 a = h[slot * NT];   // stride NT*8B: conflict-free across lanes
    a.x += bce;
    a.y += 1.0f;
    h[slot * NT] = a;
}

__global__ __launch_bounds__(NT) void ghmc_kernel(
    const float4* __restrict__ pred,
    const float4* __restrict__ targ,
    int n16,
    float* __restrict__ out) {
    __shared__ float2 hist[NCOPY * NSLOTS * NT];   // 45,056 B -> 4 CTAs/SM
    __shared__ float  s_s[NBINS], s_c[NBINS];
    __shared__ bool   s_last;

    const int tid = threadIdx.x;
    #pragma unroll
    for (int i = 0; i < NCOPY * NSLOTS; i++)
        hist[i * NT + tid] = make_float2(0.0f, 0.0f);
    __syncthreads();

    float2* h0 = &hist[tid];
    float2* h1 = &hist[NSLOTS * NT + tid];

    const int gtid = blockIdx.x * NT + tid;
    const int T    = GRID * NT;

    // 16 elements per iteration: 8 independent LDG.128 front-batched (MLP=8).
    for (int i16 = gtid; i16 < n16; i16 += T) {
        const float4* pp = pred + 4 * i16;
        const float4* tp = targ + 4 * i16;
        float4 p0 = pp[0], p1 = pp[1], p2 = pp[2], p3 = pp[3];
        float4 t0 = tp[0], t1 = tp[1], t2 = tp[2], t3 = tp[3];
        ghmc_acc(p0.x, t0.x, h0); ghmc_acc(p0.y, t0.y, h1);
        ghmc_acc(p0.z, t0.z, h0); ghmc_acc(p0.w, t0.w, h1);
        ghmc_acc(p1.x, t1.x, h0); ghmc_acc(p1.y, t1.y, h1);
        ghmc_acc(p1.z, t1.z, h0); ghmc_acc(p1.w, t1.w, h1);
        ghmc_acc(p2.x, t2.x, h0); ghmc_acc(p2.y, t2.y, h1);
        ghmc_acc(p2.z, t2.z, h0); ghmc_acc(p2.w, t2.w, h1);
        ghmc_acc(p3.x, t3.x, h0); ghmc_acc(p3.y, t3.y, h1);
        ghmc_acc(p3.z, t3.z, h0); ghmc_acc(p3.w, t3.w, h1);
    }
    __syncthreads();

    // ---- block reduction: 16 threads per bin, each sums 32 slots ----
    if (tid < NBINS * 16) {
        int bin = tid >> 4;
        int j   = tid & 15;
        float sx = 0.0f, sy = 0.0f;
        #pragma unroll
        for (int c = 0; c < NCOPY; c++) {
            #pragma unroll
            for (int k = 0; k < NT / 16; k++) {
                float2 a = hist[(c * NSLOTS + bin) * NT + j + k * 16];
                sx += a.x;
                sy += a.y;
            }
        }
        #pragma unroll
        for (int o = 8; o > 0; o >>= 1) {
            sx += __shfl_down_sync(0xffffffffu, sx, o, 16);
            sy += __shfl_down_sync(0xffffffffu, sy, o, 16);
        }
        if (j == 0)
            g_part[blockIdx.x][bin] = make_float2(sx, sy);
    }

    // ---- last-block final reduction (fused finalize) ----
    __threadfence();              // make this block's g_part row device-visible
    __syncthreads();
    if (tid == 0) {
        unsigned t = atomicAdd(&g_ticket, 1u);
        s_last = (t == GRID - 1);
    }
    __syncthreads();
    if (!s_last) return;

    __threadfence();              // acquire: see all other blocks' g_part rows
    if (tid < NBINS * 16) {
        int bin = tid >> 4;
        int j   = tid & 15;
        float sx = 0.0f, sy = 0.0f;
        for (int b = j; b < GRID; b += 16) {   // 38 independent L2-hot loads
            float2 a = g_part[b][bin];
            sx += a.x;
            sy += a.y;
        }
        #pragma unroll
        for (int o = 8; o > 0; o >>= 1) {
            sx += __shfl_down_sync(0xffffffffu, sx, o, 16);
            sy += __shfl_down_sync(0xffffffffu, sy, o, 16);
        }
        if (j == 0) { s_s[bin] = sx; s_c[bin] = sy; }
    }
    __syncthreads();
    if (tid == 0) {
        float n = 0.0f, acc = 0.0f;
        #pragma unroll
        for (int i = 0; i < NBINS; i++) {
            if (s_c[i] > 0.0f) {
                n   += 1.0f;
                acc += s_s[i] / s_c[i];
            }
        }
        out[0] = -acc / fmaxf(n, 1.0f);
        g_ticket = 0;             // reset for next graph replay (deterministic)
    }
}

extern "C" void kernel_launch(void* const* d_in, const int* in_sizes, int n_in,
                              void* d_out, int out_size) {
    const float4* pred = (const float4*)d_in[0];
    const float4* targ = (const float4*)d_in[1];
    float* out = (float*)d_out;
    int n   = in_sizes[0];
    int n16 = n >> 4;                 // 16384*4096 divisible by 16

    ghmc_kernel<<<GRID, NT>>>(pred, targ, n16, out);
}

// round 5
// speedup vs baseline: 1.4264x; 1.4264x over previous
#include <cuda_runtime.h>

#define NBINS  10
#define NSLOTS 11          // 10 real bins + dead slot for out-of-range
#define NT     256
#define NCOPY  2           // sub-histograms per thread (break smem RAW chains)
#define GRID   608         // 4 CTAs * 152 SMs (GB300)
#define TSTRIDE (GRID * NT)

// Per-block partials: every block overwrites its own slot -> no zeroing pass.
__device__ float2   g_part[GRID][NBINS];
__device__ unsigned g_ticket;   // zero-init at load; last block resets each call

__device__ __forceinline__ void ghmc_acc(float p, float t, float2* __restrict__ h) {
    // slot = min(floor(10*|p-t|), 10); slot 10 (g >= 1) is discarded.
    float g10 = fabsf(p - t) * 10.0f;
    int  slot = min((int)g10, NSLOTS - 1);

    // bce = t*p - softplus(p);  softplus(p) = max(p,0) + log(1+exp(-|p|))
    float e   = __expf(-fabsf(p));
    float l   = __logf(1.0f + e);
    float bce = t * p - fmaxf(p, 0.0f) - l;

    float2 a = h[slot * NT];   // stride NT*8B: conflict-free across lanes
    a.x += bce;
    a.y += 1.0f;
    h[slot * NT] = a;
}

__device__ __forceinline__ void ghmc_acc4(float4 p, float4 t,
                                          float2* __restrict__ h0,
                                          float2* __restrict__ h1) {
    ghmc_acc(p.x, t.x, h0);
    ghmc_acc(p.y, t.y, h1);
    ghmc_acc(p.z, t.z, h0);
    ghmc_acc(p.w, t.w, h1);
}

__global__ __launch_bounds__(NT) void ghmc_kernel(
    const float4* __restrict__ pred,
    const float4* __restrict__ targ,
    int n4, int full_iters,
    float* __restrict__ out) {
    __shared__ float2 hist[NCOPY * NSLOTS * NT];   // 45,056 B -> 4 CTAs/SM
    __shared__ float  s_s[NBINS], s_c[NBINS];
    __shared__ bool   s_last;

    const int tid = threadIdx.x;
    #pragma unroll
    for (int i = 0; i < NCOPY * NSLOTS; i++)
        hist[i * NT + tid] = make_float2(0.0f, 0.0f);
    __syncthreads();

    float2* h0 = &hist[tid];
    float2* h1 = &hist[NSLOTS * NT + tid];

    int i = blockIdx.x * NT + tid;

    // Main loop: 4 coalesced LDG.128 per array per iter (MLP=8), each load
    // consecutive-lane-consecutive-float4 -> 4 lines/load (L1 wavefront floor).
    for (int k = 0; k < full_iters; k++) {
        float4 pa = pred[i];
        float4 pb = pred[i + TSTRIDE];
        float4 pc = pred[i + 2 * TSTRIDE];
        float4 pd = pred[i + 3 * TSTRIDE];
        float4 ta = targ[i];
        float4 tb = targ[i + TSTRIDE];
        float4 tc = targ[i + 2 * TSTRIDE];
        float4 td = targ[i + 3 * TSTRIDE];
        ghmc_acc4(pa, ta, h0, h1);
        ghmc_acc4(pb, tb, h0, h1);
        ghmc_acc4(pc, tc, h0, h1);
        ghmc_acc4(pd, td, h0, h1);
        i += 4 * TSTRIDE;
    }
    // Remainder: plain grid-stride, still coalesced.
    for (; i < n4; i += TSTRIDE) {
        float4 p = pred[i];
        float4 t = targ[i];
        ghmc_acc4(p, t, h0, h1);
    }
    __syncthreads();

    // ---- block reduction: 16 threads per bin, each sums 32 slots ----
    if (tid < NBINS * 16) {
        int bin = tid >> 4;
        int j   = tid & 15;
        float sx = 0.0f, sy = 0.0f;
        #pragma unroll
        for (int c = 0; c < NCOPY; c++) {
            #pragma unroll
            for (int k = 0; k < NT / 16; k++) {
                float2 a = hist[(c * NSLOTS + bin) * NT + j + k * 16];
                sx += a.x;
                sy += a.y;
            }
        }
        #pragma unroll
        for (int o = 8; o > 0; o >>= 1) {
            sx += __shfl_down_sync(0xffffffffu, sx, o, 16);
            sy += __shfl_down_sync(0xffffffffu, sy, o, 16);
        }
        if (j == 0)
            g_part[blockIdx.x][bin] = make_float2(sx, sy);
    }

    // ---- last-block final reduction (fused finalize) ----
    __threadfence();
    __syncthreads();
    if (tid == 0) {
        unsigned t = atomicAdd(&g_ticket, 1u);
        s_last = (t == GRID - 1);
    }
    __syncthreads();
    if (!s_last) return;

    __threadfence();
    if (tid < NBINS * 16) {
        int bin = tid >> 4;
        int j   = tid & 15;
        float sx = 0.0f, sy = 0.0f;
        for (int b = j; b < GRID; b += 16) {
            float2 a = g_part[b][bin];
            sx += a.x;
            sy += a.y;
        }
        #pragma unroll
        for (int o = 8; o > 0; o >>= 1) {
            sx += __shfl_down_sync(0xffffffffu, sx, o, 16);
            sy += __shfl_down_sync(0xffffffffu, sy, o, 16);
        }
        if (j == 0) { s_s[bin] = sx; s_c[bin] = sy; }
    }
    __syncthreads();
    if (tid == 0) {
        float n = 0.0f, acc = 0.0f;
        #pragma unroll
        for (int i2 = 0; i2 < NBINS; i2++) {
            if (s_c[i2] > 0.0f) {
                n   += 1.0f;
                acc += s_s[i2] / s_c[i2];
            }
        }
        out[0] = -acc / fmaxf(n, 1.0f);
        g_ticket = 0;   // reset for next graph replay
    }
}

extern "C" void kernel_launch(void* const* d_in, const int* in_sizes, int n_in,
                              void* d_out, int out_size) {
    const float4* pred = (const float4*)d_in[0];
    const float4* targ = (const float4*)d_in[1];
    float* out = (float*)d_out;
    int n  = in_sizes[0];
    int n4 = n >> 2;                          // n divisible by 4
    int full_iters = n4 / (4 * TSTRIDE);      // unrolled main-loop trip count

    ghmc_kernel<<<GRID, NT>>>(pred, targ, n4, full_iters, out);
}

// round 6
// speedup vs baseline: 1.5302x; 1.0727x over previous
#include <cuda_runtime.h>

#define NBINS  10
#define NSLOTS 11          // 10 real bins + dead slot for out-of-range (g >= 1)
#define NT     256
#define GRID   1216        // 8 CTAs * 152 SMs (GB300) -> 100% occupancy
#define TSTRIDE (GRID * NT)

// Per-block partials: every block overwrites its own slot -> no zeroing pass.
__device__ float2   g_part[GRID][NBINS];
__device__ unsigned g_ticket;   // zero-init at load; last block resets each call

__device__ __forceinline__ void ghmc_acc(float p, float t, float2* __restrict__ h) {
    // slot = min(floor(10*|p-t|), 10); slot 10 is discarded.
    float g10 = fabsf(p - t) * 10.0f;
    int  slot = min((int)g10, NSLOTS - 1);

    // bce = t*p - softplus(p);  softplus(p) = max(p,0) + log(1+exp(-|p|))
    float e   = __expf(-fabsf(p));
    float l   = __logf(1.0f + e);
    float bce = t * p - fmaxf(p, 0.0f) - l;

    float2 a = h[slot * NT];   // stride NT*8B: conflict-free across lanes
    a.x += bce;
    a.y += 1.0f;
    h[slot * NT] = a;
}

__device__ __forceinline__ void ghmc_acc4(float4 p, float4 t,
                                          float2* __restrict__ h) {
    ghmc_acc(p.x, t.x, h);
    ghmc_acc(p.y, t.y, h);
    ghmc_acc(p.z, t.z, h);
    ghmc_acc(p.w, t.w, h);
}

__global__ __launch_bounds__(NT) void ghmc_kernel(
    const float4* __restrict__ pred,
    const float4* __restrict__ targ,
    int n4, int full_iters,
    float* __restrict__ out) {
    __shared__ float2 hist[NSLOTS * NT];   // 22,528 B -> 8 CTAs/SM
    __shared__ float  s_s[NBINS], s_c[NBINS];
    __shared__ bool   s_last;

    const int tid = threadIdx.x;
    #pragma unroll
    for (int i = 0; i < NSLOTS; i++)
        hist[i * NT + tid] = make_float2(0.0f, 0.0f);
    __syncthreads();

    float2* h = &hist[tid];

    int i = blockIdx.x * NT + tid;

    // Main loop: 4 coalesced LDG.128 front-batched per iter (each load touches
    // exactly 4 lines — the L1 wavefront floor).
    for (int k = 0; k < full_iters; k++) {
        float4 pa = pred[i];
        float4 pb = pred[i + TSTRIDE];
        float4 ta = targ[i];
        float4 tb = targ[i + TSTRIDE];
        ghmc_acc4(pa, ta, h);
        ghmc_acc4(pb, tb, h);
        i += 2 * TSTRIDE;
    }
    // Remainder: plain grid-stride, still coalesced.
    for (; i < n4; i += TSTRIDE) {
        float4 p = pred[i];
        float4 t = targ[i];
        ghmc_acc4(p, t, h);
    }
    __syncthreads();

    // ---- block reduction: 16 threads per bin, each sums 16 slots ----
    if (tid < NBINS * 16) {
        int bin = tid >> 4;
        int j   = tid & 15;
        float sx = 0.0f, sy = 0.0f;
        #pragma unroll
        for (int k = 0; k < NT / 16; k++) {
            float2 a = hist[bin * NT + j + k * 16];
            sx += a.x;
            sy += a.y;
        }
        #pragma unroll
        for (int o = 8; o > 0; o >>= 1) {
            sx += __shfl_down_sync(0xffffffffu, sx, o, 16);
            sy += __shfl_down_sync(0xffffffffu, sy, o, 16);
        }
        if (j == 0)
            g_part[blockIdx.x][bin] = make_float2(sx, sy);
    }

    // ---- last-block final reduction (fused finalize) ----
    __threadfence();
    __syncthreads();
    if (tid == 0) {
        unsigned t = atomicAdd(&g_ticket, 1u);
        s_last = (t == GRID - 1);
    }
    __syncthreads();
    if (!s_last) return;

    __threadfence();
    if (tid < NBINS * 16) {
        int bin = tid >> 4;
        int j   = tid & 15;
        float sx = 0.0f, sy = 0.0f;
        for (int b = j; b < GRID; b += 16) {   // 76 L2-hot loads per thread
            float2 a = g_part[b][bin];
            sx += a.x;
            sy += a.y;
        }
        #pragma unroll
        for (int o = 8; o > 0; o >>= 1) {
            sx += __shfl_down_sync(0xffffffffu, sx, o, 16);
            sy += __shfl_down_sync(0xffffffffu, sy, o, 16);
        }
        if (j == 0) { s_s[bin] = sx; s_c[bin] = sy; }
    }
    __syncthreads();
    if (tid == 0) {
        float n = 0.0f, acc = 0.0f;
        #pragma unroll
        for (int i2 = 0; i2 < NBINS; i2++) {
            if (s_c[i2] > 0.0f) {
                n   += 1.0f;
                acc += s_s[i2] / s_c[i2];
            }
        }
        out[0] = -acc / fmaxf(n, 1.0f);
        g_ticket = 0;   // reset for next graph replay
    }
}

extern "C" void kernel_launch(void* const* d_in, const int* in_sizes, int n_in,
                              void* d_out, int out_size) {
    const float4* pred = (const float4*)d_in[0];
    const float4* targ = (const float4*)d_in[1];
    float* out = (float*)d_out;
    int n  = in_sizes[0];
    int n4 = n >> 2;                          // n divisible by 4
    int full_iters = n4 / (2 * TSTRIDE);      // unrolled main-loop trip count

    ghmc_kernel<<<GRID, NT>>>(pred, targ, n4, full_iters, out);
}